// round 1
// baseline (speedup 1.0000x reference)
#include <cuda_runtime.h>
#include <cuda_bf16.h>
#include <math.h>

// Problem constants (fixed shapes per reference):
//   x: [4, 64, 256, 256] fp32, units: [256, 64] fp32
#define HDIM 64
#define KDIM 256
#define HW   65536           // 256*256
#define NPTS 262144          // 4*65536
#define RATE_F 0.999f
#define EPS_F  1e-6f

// Persistent device scratch (no runtime allocation allowed).
__device__ __align__(16) float g_m  [KDIM * HDIM];   // current (unnormalized) codebook
__device__ __align__(16) float g_mn [KDIM * HDIM];   // row-normalized codebook
__device__ __align__(16) float g_sum[KDIM * HDIM];   // segment sums (atomic targets)
__device__ __align__(16) float g_cnt[KDIM];          // segment counts

// ---------------------------------------------------------------------------
// prep: m = units; mn = normalize(m); zero sums/counts.
// grid: 32 CTAs x 256 threads, warp per codebook row (8 rows/CTA).
// ---------------------------------------------------------------------------
__global__ void prep_kernel(const float* __restrict__ units) {
    int warp = threadIdx.x >> 5;
    int lane = threadIdx.x & 31;
    int k = blockIdx.x * 8 + warp;
    if (k >= KDIM) return;
    float v0 = units[k * HDIM + lane];
    float v1 = units[k * HDIM + 32 + lane];
    g_m[k * HDIM + lane]      = v0;
    g_m[k * HDIM + 32 + lane] = v1;
    float ssq = v0 * v0 + v1 * v1;
    #pragma unroll
    for (int o = 16; o; o >>= 1) ssq += __shfl_xor_sync(0xFFFFFFFFu, ssq, o);
    float inv = 1.0f / fmaxf(sqrtf(ssq), 1e-12f);
    g_mn[k * HDIM + lane]      = v0 * inv;
    g_mn[k * HDIM + 32 + lane] = v1 * inv;
    g_sum[k * HDIM + lane]      = 0.0f;
    g_sum[k * HDIM + 32 + lane] = 0.0f;
    if (lane == 0) g_cnt[k] = 0.0f;
}

// ---------------------------------------------------------------------------
// assign: per point, argmax_k (xf . mn_k)  (invnorm > 0 => argmax-invariant),
// then scatter xf into g_sum[argmax], count into g_cnt.
// grid: NPTS/256 CTAs x 256 threads, one point per thread.
// dyn smem: 64 KB (mn).
// ---------------------------------------------------------------------------
__global__ void __launch_bounds__(256) assign_kernel(const float* __restrict__ x) {
    extern __shared__ float smn[];  // KDIM*HDIM = 16384 floats
    #pragma unroll 4
    for (int i = threadIdx.x; i < KDIM * HDIM; i += 256) smn[i] = g_mn[i];
    __syncthreads();

    int p  = blockIdx.x * 256 + threadIdx.x;     // linear point id over (b,h,w)
    int b  = p >> 16;
    int hw = p & (HW - 1);
    const float* xb = x + (size_t)b * HDIM * HW + hw;

    float xr[HDIM];
    #pragma unroll
    for (int c = 0; c < HDIM; c++) xr[c] = xb[(size_t)c * HW];

    float best = -1e30f;
    int   bi   = 0;
    #pragma unroll 2
    for (int k = 0; k < KDIM; k++) {
        const float4* mr = (const float4*)(smn + k * HDIM);
        float d0 = 0.f, d1 = 0.f, d2 = 0.f, d3 = 0.f;
        #pragma unroll
        for (int i = 0; i < 16; i++) {
            float4 v = mr[i];
            d0 = fmaf(xr[4 * i + 0], v.x, d0);
            d1 = fmaf(xr[4 * i + 1], v.y, d1);
            d2 = fmaf(xr[4 * i + 2], v.z, d2);
            d3 = fmaf(xr[4 * i + 3], v.w, d3);
        }
        float d = (d0 + d1) + (d2 + d3);
        if (d > best) { best = d; bi = k; }
    }

    float* dst = g_sum + bi * HDIM;
    #pragma unroll
    for (int i = 0; i < 16; i++) {
        asm volatile("red.global.add.v4.f32 [%0], {%1,%2,%3,%4};"
                     :: "l"(dst + 4 * i),
                        "f"(xr[4 * i + 0]), "f"(xr[4 * i + 1]),
                        "f"(xr[4 * i + 2]), "f"(xr[4 * i + 3])
                     : "memory");
    }
    atomicAdd(g_cnt + bi, 1.0f);
}

// ---------------------------------------------------------------------------
// update: m = m*RATE + (sum/(cnt+eps))*(1-RATE); mn = normalize(m);
// then zero sums/counts for the next iteration.
// ---------------------------------------------------------------------------
__global__ void update_kernel() {
    int warp = threadIdx.x >> 5;
    int lane = threadIdx.x & 31;
    int k = blockIdx.x * 8 + warp;
    if (k >= KDIM) return;
    const float IR = 1.0f - RATE_F;
    float cnt = g_cnt[k];
    float sc  = IR / (cnt + EPS_F);
    float m0 = g_m[k * HDIM + lane]      * RATE_F + g_sum[k * HDIM + lane]      * sc;
    float m1 = g_m[k * HDIM + 32 + lane] * RATE_F + g_sum[k * HDIM + 32 + lane] * sc;
    g_m[k * HDIM + lane]      = m0;
    g_m[k * HDIM + 32 + lane] = m1;
    float ssq = m0 * m0 + m1 * m1;
    #pragma unroll
    for (int o = 16; o; o >>= 1) ssq += __shfl_xor_sync(0xFFFFFFFFu, ssq, o);
    float inv = 1.0f / fmaxf(sqrtf(ssq), 1e-12f);
    g_mn[k * HDIM + lane]      = m0 * inv;
    g_mn[k * HDIM + 32 + lane] = m1 * inv;
    g_sum[k * HDIM + lane]      = 0.0f;
    g_sum[k * HDIM + 32 + lane] = 0.0f;
    if (lane == 0) g_cnt[k] = 0.0f;
}

// ---------------------------------------------------------------------------
// out: per point, s_k = invn*(xf.mn_k); softmax over k; out = sum_k p_k * m_k.
// Two passes over k (max, then exp+accumulate). Writes [b,c,h,w] coalesced.
// dyn smem: 128 KB (mn then m).
// ---------------------------------------------------------------------------
__global__ void __launch_bounds__(256, 1) out_kernel(const float* __restrict__ x,
                                                     float* __restrict__ out) {
    extern __shared__ float sm[];   // [0,16384): mn   [16384,32768): m
    #pragma unroll 4
    for (int i = threadIdx.x; i < KDIM * HDIM; i += 256) {
        sm[i]               = g_mn[i];
        sm[KDIM * HDIM + i] = g_m[i];
    }
    __syncthreads();

    int p  = blockIdx.x * 256 + threadIdx.x;
    int b  = p >> 16;
    int hw = p & (HW - 1);
    const float* xb = x + (size_t)b * HDIM * HW + hw;

    float xr[HDIM];
    float s0 = 0.f, s1 = 0.f, s2 = 0.f, s3 = 0.f;
    #pragma unroll
    for (int c = 0; c < HDIM; c += 4) {
        xr[c + 0] = xb[(size_t)(c + 0) * HW];
        xr[c + 1] = xb[(size_t)(c + 1) * HW];
        xr[c + 2] = xb[(size_t)(c + 2) * HW];
        xr[c + 3] = xb[(size_t)(c + 3) * HW];
        s0 = fmaf(xr[c + 0], xr[c + 0], s0);
        s1 = fmaf(xr[c + 1], xr[c + 1], s1);
        s2 = fmaf(xr[c + 2], xr[c + 2], s2);
        s3 = fmaf(xr[c + 3], xr[c + 3], s3);
    }
    float nrm  = sqrtf((s0 + s1) + (s2 + s3));
    float invn = 1.0f / fmaxf(nrm, 1e-12f);

    // Pass A: max dot (invn>0 constant => max(dot)*invn == max(score))
    float mxd = -1e30f;
    #pragma unroll 2
    for (int k = 0; k < KDIM; k++) {
        const float4* mr = (const float4*)(sm + k * HDIM);
        float d0 = 0.f, d1 = 0.f, d2 = 0.f, d3 = 0.f;
        #pragma unroll
        for (int i = 0; i < 16; i++) {
            float4 v = mr[i];
            d0 = fmaf(xr[4 * i + 0], v.x, d0);
            d1 = fmaf(xr[4 * i + 1], v.y, d1);
            d2 = fmaf(xr[4 * i + 2], v.z, d2);
            d3 = fmaf(xr[4 * i + 3], v.w, d3);
        }
        float d = (d0 + d1) + (d2 + d3);
        mxd = fmaxf(mxd, d);
    }
    float mx = mxd * invn;

    // Pass B: exp-weighted accumulation of m.
    float acc[HDIM];
    #pragma unroll
    for (int c = 0; c < HDIM; c++) acc[c] = 0.0f;
    float den = 0.0f;

    for (int k = 0; k < KDIM; k++) {
        const float4* mr = (const float4*)(sm + k * HDIM);
        float d0 = 0.f, d1 = 0.f, d2 = 0.f, d3 = 0.f;
        #pragma unroll
        for (int i = 0; i < 16; i++) {
            float4 v = mr[i];
            d0 = fmaf(xr[4 * i + 0], v.x, d0);
            d1 = fmaf(xr[4 * i + 1], v.y, d1);
            d2 = fmaf(xr[4 * i + 2], v.z, d2);
            d3 = fmaf(xr[4 * i + 3], v.w, d3);
        }
        float d = (d0 + d1) + (d2 + d3);
        float e = __expf(fmaf(d, invn, -mx));
        den += e;
        const float4* wr = (const float4*)(sm + KDIM * HDIM + k * HDIM);
        #pragma unroll
        for (int i = 0; i < 16; i++) {
            float4 w = wr[i];
            acc[4 * i + 0] = fmaf(e, w.x, acc[4 * i + 0]);
            acc[4 * i + 1] = fmaf(e, w.y, acc[4 * i + 1]);
            acc[4 * i + 2] = fmaf(e, w.z, acc[4 * i + 2]);
            acc[4 * i + 3] = fmaf(e, w.w, acc[4 * i + 3]);
        }
    }

    float iden = 1.0f / den;
    float* ob = out + (size_t)b * HDIM * HW + hw;
    #pragma unroll
    for (int c = 0; c < HDIM; c++) ob[(size_t)c * HW] = acc[c] * iden;
}

// ---------------------------------------------------------------------------
extern "C" void kernel_launch(void* const* d_in, const int* in_sizes, int n_in,
                              void* d_out, int out_size) {
    // metadata order: x (16777216), units (16384); be defensive about order.
    const float* x;
    const float* units;
    if (in_sizes[0] >= in_sizes[1]) { x = (const float*)d_in[0]; units = (const float*)d_in[1]; }
    else                            { x = (const float*)d_in[1]; units = (const float*)d_in[0]; }
    float* out = (float*)d_out;

    // Allow >48KB dynamic smem (idempotent host-side attribute sets; not stream ops).
    cudaFuncSetAttribute(assign_kernel, cudaFuncAttributeMaxDynamicSharedMemorySize,
                         KDIM * HDIM * (int)sizeof(float));
    cudaFuncSetAttribute(out_kernel, cudaFuncAttributeMaxDynamicSharedMemorySize,
                         2 * KDIM * HDIM * (int)sizeof(float));

    const int ngrid = NPTS / 256;

    prep_kernel<<<32, 256>>>(units);
    for (int it = 0; it < 3; it++) {
        assign_kernel<<<ngrid, 256, KDIM * HDIM * sizeof(float)>>>(x);
        update_kernel<<<32, 256>>>();
    }
    out_kernel<<<ngrid, 256, 2 * KDIM * HDIM * sizeof(float)>>>(x, out);
}

// round 2
// speedup vs baseline: 1.4748x; 1.4748x over previous
#include <cuda_runtime.h>
#include <cuda_bf16.h>
#include <math.h>

#define HDIM 64
#define KDIM 256
#define HW   65536
#define NPTS 262144
#define RATE_F 0.999f
#define EPS_F  1e-6f

typedef unsigned long long u64;

// Persistent device scratch (allocation-free rule).
__device__ __align__(16) float g_m  [KDIM * HDIM];
__device__ __align__(16) float g_mn [KDIM * HDIM];
__device__ __align__(16) float g_sum[KDIM * HDIM];
__device__ float g_cnt[KDIM];
__device__ float g_nrm[KDIM];

// ---- packed f32x2 helpers (FFMA2: 2 FMAs / instruction on sm_103a) ----
__device__ __forceinline__ u64 pack2(float lo, float hi) {
    u64 r; asm("mov.b64 %0, {%1, %2};" : "=l"(r) : "f"(lo), "f"(hi)); return r;
}
__device__ __forceinline__ void unpack2(u64 v, float& lo, float& hi) {
    asm("mov.b64 {%0, %1}, %2;" : "=f"(lo), "=f"(hi) : "l"(v));
}
__device__ __forceinline__ void fma2(u64& d, u64 a, u64 b) {
    asm("fma.rn.f32x2 %0, %1, %2, %0;" : "+l"(d) : "l"(a), "l"(b));
}

// ---------------------------------------------------------------------------
// prep: m = units; mn = normalize(m); nrm = |m|; zero sums/counts.
// ---------------------------------------------------------------------------
__global__ void prep_kernel(const float* __restrict__ units) {
    int warp = threadIdx.x >> 5, lane = threadIdx.x & 31;
    int k = blockIdx.x * 8 + warp;
    if (k >= KDIM) return;
    float v0 = units[k * HDIM + lane];
    float v1 = units[k * HDIM + 32 + lane];
    g_m[k * HDIM + lane]      = v0;
    g_m[k * HDIM + 32 + lane] = v1;
    float ssq = v0 * v0 + v1 * v1;
    #pragma unroll
    for (int o = 16; o; o >>= 1) ssq += __shfl_xor_sync(0xFFFFFFFFu, ssq, o);
    float nrm = sqrtf(ssq);
    float inv = 1.0f / fmaxf(nrm, 1e-12f);
    g_mn[k * HDIM + lane]      = v0 * inv;
    g_mn[k * HDIM + 32 + lane] = v1 * inv;
    g_sum[k * HDIM + lane]      = 0.0f;
    g_sum[k * HDIM + 32 + lane] = 0.0f;
    if (lane == 0) { g_cnt[k] = 0.0f; g_nrm[k] = nrm; }
}

// ---------------------------------------------------------------------------
// assign: 2 points/thread, argmax over k of (xf . mn_k), scatter EMA sums.
// grid = NPTS/512 CTAs x 256 threads. dyn smem = 64 KB (mn).
// ---------------------------------------------------------------------------
__global__ void __launch_bounds__(256) assign_kernel(const float* __restrict__ x) {
    extern __shared__ ulonglong2 smq[];          // 4096 x 16B = mn tile
    const ulonglong2* gm = (const ulonglong2*)g_mn;
    #pragma unroll 4
    for (int i = threadIdx.x; i < KDIM * HDIM / 4; i += 256) smq[i] = gm[i];
    __syncthreads();

    int t  = blockIdx.x * 256 + threadIdx.x;
    int p0 = t, p1 = t + NPTS / 2;
    int b0 = p0 >> 16, b1 = p1 >> 16;
    const float* xa_p = x + (size_t)b0 * HDIM * HW + (p0 & (HW - 1));
    const float* xb_p = x + (size_t)b1 * HDIM * HW + (p1 & (HW - 1));

    u64 xa[HDIM / 2], xb[HDIM / 2];
    #pragma unroll
    for (int i = 0; i < HDIM / 2; i++) {
        xa[i] = pack2(xa_p[(size_t)(2 * i) * HW], xa_p[(size_t)(2 * i + 1) * HW]);
        xb[i] = pack2(xb_p[(size_t)(2 * i) * HW], xb_p[(size_t)(2 * i + 1) * HW]);
    }

    float bestA = -1e30f, bestB = -1e30f;
    int   biA = 0, biB = 0;
    for (int k = 0; k < KDIM; k++) {
        u64 da0 = 0ull, da1 = 0ull, db0 = 0ull, db1 = 0ull;  // {0,0} packed
        const ulonglong2* row = smq + k * 16;
        #pragma unroll
        for (int i = 0; i < 16; i++) {
            ulonglong2 q = row[i];
            fma2(da0, xa[2 * i],     q.x);
            fma2(da1, xa[2 * i + 1], q.y);
            fma2(db0, xb[2 * i],     q.x);
            fma2(db1, xb[2 * i + 1], q.y);
        }
        float a0, a1, a2, a3, c0, c1, c2, c3;
        unpack2(da0, a0, a1); unpack2(da1, a2, a3);
        unpack2(db0, c0, c1); unpack2(db1, c2, c3);
        float dA = (a0 + a1) + (a2 + a3);
        float dB = (c0 + c1) + (c2 + c3);
        if (dA > bestA) { bestA = dA; biA = k; }
        if (dB > bestB) { bestB = dB; biB = k; }
    }

    float* dstA = g_sum + biA * HDIM;
    #pragma unroll
    for (int i = 0; i < 16; i++) {
        float f0, f1, f2, f3;
        unpack2(xa[2 * i], f0, f1); unpack2(xa[2 * i + 1], f2, f3);
        asm volatile("red.global.add.v4.f32 [%0], {%1,%2,%3,%4};"
                     :: "l"(dstA + 4 * i), "f"(f0), "f"(f1), "f"(f2), "f"(f3) : "memory");
    }
    atomicAdd(g_cnt + biA, 1.0f);

    float* dstB = g_sum + biB * HDIM;
    #pragma unroll
    for (int i = 0; i < 16; i++) {
        float f0, f1, f2, f3;
        unpack2(xb[2 * i], f0, f1); unpack2(xb[2 * i + 1], f2, f3);
        asm volatile("red.global.add.v4.f32 [%0], {%1,%2,%3,%4};"
                     :: "l"(dstB + 4 * i), "f"(f0), "f"(f1), "f"(f2), "f"(f3) : "memory");
    }
    atomicAdd(g_cnt + biB, 1.0f);
}

// ---------------------------------------------------------------------------
// update: m = m*RATE + (sum/(cnt+eps))*(1-RATE); refresh mn, nrm; zero sums.
// ---------------------------------------------------------------------------
__global__ void update_kernel() {
    int warp = threadIdx.x >> 5, lane = threadIdx.x & 31;
    int k = blockIdx.x * 8 + warp;
    if (k >= KDIM) return;
    const float IR = 1.0f - RATE_F;
    float sc = IR / (g_cnt[k] + EPS_F);
    float m0 = g_m[k * HDIM + lane]      * RATE_F + g_sum[k * HDIM + lane]      * sc;
    float m1 = g_m[k * HDIM + 32 + lane] * RATE_F + g_sum[k * HDIM + 32 + lane] * sc;
    g_m[k * HDIM + lane]      = m0;
    g_m[k * HDIM + 32 + lane] = m1;
    float ssq = m0 * m0 + m1 * m1;
    #pragma unroll
    for (int o = 16; o; o >>= 1) ssq += __shfl_xor_sync(0xFFFFFFFFu, ssq, o);
    float nrm = sqrtf(ssq);
    float inv = 1.0f / fmaxf(nrm, 1e-12f);
    g_mn[k * HDIM + lane]      = m0 * inv;
    g_mn[k * HDIM + 32 + lane] = m1 * inv;
    g_sum[k * HDIM + lane]      = 0.0f;
    g_sum[k * HDIM + 32 + lane] = 0.0f;
    if (lane == 0) { g_cnt[k] = 0.0f; g_nrm[k] = nrm; }
}

// ---------------------------------------------------------------------------
// out: single pass (score in [-1,1] => exp safe without max-shift).
// m_k reconstructed as mn_k * nrm_k so one mn row load serves dot AND acc.
// dyn smem = 64 KB mn + 1 KB nrm. grid = NPTS/256 x 256.
// ---------------------------------------------------------------------------
__global__ void __launch_bounds__(256, 1) out_kernel(const float* __restrict__ x,
                                                     float* __restrict__ out) {
    extern __shared__ ulonglong2 smem_raw[];
    ulonglong2* smq = smem_raw;                                  // mn: 4096 x 16B
    float* snrm = (float*)(smem_raw + KDIM * HDIM / 4);          // nrm: 256 floats
    const ulonglong2* gm = (const ulonglong2*)g_mn;
    #pragma unroll 4
    for (int i = threadIdx.x; i < KDIM * HDIM / 4; i += 256) smq[i] = gm[i];
    if (threadIdx.x < KDIM) snrm[threadIdx.x] = g_nrm[threadIdx.x];
    __syncthreads();

    int p  = blockIdx.x * 256 + threadIdx.x;
    int b  = p >> 16;
    const float* xb = x + (size_t)b * HDIM * HW + (p & (HW - 1));

    u64 xr[HDIM / 2];
    float s0 = 0.f, s1 = 0.f;
    #pragma unroll
    for (int i = 0; i < HDIM / 2; i++) {
        float f0 = xb[(size_t)(2 * i) * HW];
        float f1 = xb[(size_t)(2 * i + 1) * HW];
        xr[i] = pack2(f0, f1);
        s0 = fmaf(f0, f0, s0);
        s1 = fmaf(f1, f1, s1);
    }
    float invn = 1.0f / fmaxf(sqrtf(s0 + s1), 1e-12f);

    u64 acc[HDIM / 2];
    #pragma unroll
    for (int i = 0; i < HDIM / 2; i++) acc[i] = 0ull;
    float den = 0.0f;

    for (int k = 0; k < KDIM; k++) {
        u64 v[HDIM / 2];
        const ulonglong2* row = smq + k * 16;
        #pragma unroll
        for (int i = 0; i < 16; i++) { ulonglong2 q = row[i]; v[2 * i] = q.x; v[2 * i + 1] = q.y; }

        u64 d0 = 0ull, d1 = 0ull;
        #pragma unroll
        for (int i = 0; i < 16; i++) {
            fma2(d0, xr[2 * i],     v[2 * i]);
            fma2(d1, xr[2 * i + 1], v[2 * i + 1]);
        }
        float e0, e1, e2, e3;
        unpack2(d0, e0, e1); unpack2(d1, e2, e3);
        float d = (e0 + e1) + (e2 + e3);
        float e = __expf(d * invn);
        den += e;
        u64 w2 = pack2(e * snrm[k], e * snrm[k]);
        #pragma unroll
        for (int i = 0; i < HDIM / 2; i++) fma2(acc[i], w2, v[i]);
    }

    float iden = 1.0f / den;
    float* ob = out + (size_t)b * HDIM * HW + (p & (HW - 1));
    #pragma unroll
    for (int i = 0; i < HDIM / 2; i++) {
        float f0, f1;
        unpack2(acc[i], f0, f1);
        ob[(size_t)(2 * i) * HW]     = f0 * iden;
        ob[(size_t)(2 * i + 1) * HW] = f1 * iden;
    }
}

// ---------------------------------------------------------------------------
extern "C" void kernel_launch(void* const* d_in, const int* in_sizes, int n_in,
                              void* d_out, int out_size) {
    const float* x;
    const float* units;
    if (in_sizes[0] >= in_sizes[1]) { x = (const float*)d_in[0]; units = (const float*)d_in[1]; }
    else                            { x = (const float*)d_in[1]; units = (const float*)d_in[0]; }
    float* out = (float*)d_out;

    const int mn_bytes  = KDIM * HDIM * (int)sizeof(float);          // 64 KB
    const int out_bytes = mn_bytes + KDIM * (int)sizeof(float);     // 65 KB
    cudaFuncSetAttribute(assign_kernel, cudaFuncAttributeMaxDynamicSharedMemorySize, mn_bytes);
    cudaFuncSetAttribute(out_kernel,    cudaFuncAttributeMaxDynamicSharedMemorySize, out_bytes);

    prep_kernel<<<32, 256>>>(units);
    for (int it = 0; it < 3; it++) {
        assign_kernel<<<NPTS / 512, 256, mn_bytes>>>(x);
        update_kernel<<<32, 256>>>();
    }
    out_kernel<<<NPTS / 256, 256, out_bytes>>>(x, out);
}

// round 3
// speedup vs baseline: 1.4751x; 1.0003x over previous
#include <cuda_runtime.h>
#include <cuda_bf16.h>
#include <math.h>

#define HDIM 64
#define KDIM 256
#define HW   65536
#define NPTS 262144
#define RATE_F 0.999f
#define EPS_F  1e-6f

typedef unsigned long long u64;

// Persistent device scratch (allocation-free rule).
__device__ __align__(16) float g_m  [KDIM * HDIM];
__device__ __align__(16) float g_mn [KDIM * HDIM];
__device__ __align__(16) float g_sum[KDIM * HDIM];
__device__ float g_cnt[KDIM];
__device__ float g_nrm[KDIM];

// ---- packed f32x2 helpers (FFMA2: 2 FMAs / instruction on sm_103a) ----
__device__ __forceinline__ u64 pack2(float lo, float hi) {
    u64 r; asm("mov.b64 %0, {%1, %2};" : "=l"(r) : "f"(lo), "f"(hi)); return r;
}
__device__ __forceinline__ void unpack2(u64 v, float& lo, float& hi) {
    asm("mov.b64 {%0, %1}, %2;" : "=f"(lo), "=f"(hi) : "l"(v));
}
__device__ __forceinline__ void fma2(u64& d, u64 a, u64 b) {
    asm("fma.rn.f32x2 %0, %1, %2, %0;" : "+l"(d) : "l"(a), "l"(b));
}

// ---------------------------------------------------------------------------
// prep: m = units; mn = normalize(m); nrm = |m|; zero sums/counts.
// ---------------------------------------------------------------------------
__global__ void prep_kernel(const float* __restrict__ units) {
    int warp = threadIdx.x >> 5, lane = threadIdx.x & 31;
    int k = blockIdx.x * 8 + warp;
    if (k >= KDIM) return;
    float v0 = units[k * HDIM + lane];
    float v1 = units[k * HDIM + 32 + lane];
    g_m[k * HDIM + lane]      = v0;
    g_m[k * HDIM + 32 + lane] = v1;
    float ssq = v0 * v0 + v1 * v1;
    #pragma unroll
    for (int o = 16; o; o >>= 1) ssq += __shfl_xor_sync(0xFFFFFFFFu, ssq, o);
    float nrm = sqrtf(ssq);
    float inv = 1.0f / fmaxf(nrm, 1e-12f);
    g_mn[k * HDIM + lane]      = v0 * inv;
    g_mn[k * HDIM + 32 + lane] = v1 * inv;
    g_sum[k * HDIM + lane]      = 0.0f;
    g_sum[k * HDIM + 32 + lane] = 0.0f;
    if (lane == 0) { g_cnt[k] = 0.0f; g_nrm[k] = nrm; }
}

// ---------------------------------------------------------------------------
// assign: 2 points/thread, argmax over k of (xf . mn_k), scatter EMA sums.
// grid = NPTS/512 CTAs x 256 threads. dyn smem = 64 KB (mn).
// ---------------------------------------------------------------------------
__global__ void __launch_bounds__(256) assign_kernel(const float* __restrict__ x) {
    extern __shared__ ulonglong2 smq[];          // 4096 x 16B = mn tile
    const ulonglong2* gm = (const ulonglong2*)g_mn;
    #pragma unroll 4
    for (int i = threadIdx.x; i < KDIM * HDIM / 4; i += 256) smq[i] = gm[i];
    __syncthreads();

    int t  = blockIdx.x * 256 + threadIdx.x;
    int p0 = t, p1 = t + NPTS / 2;
    int b0 = p0 >> 16, b1 = p1 >> 16;
    const float* xa_p = x + (size_t)b0 * HDIM * HW + (p0 & (HW - 1));
    const float* xb_p = x + (size_t)b1 * HDIM * HW + (p1 & (HW - 1));

    u64 xa[HDIM / 2], xb[HDIM / 2];
    #pragma unroll
    for (int i = 0; i < HDIM / 2; i++) {
        xa[i] = pack2(xa_p[(size_t)(2 * i) * HW], xa_p[(size_t)(2 * i + 1) * HW]);
        xb[i] = pack2(xb_p[(size_t)(2 * i) * HW], xb_p[(size_t)(2 * i + 1) * HW]);
    }

    float bestA = -1e30f, bestB = -1e30f;
    int   biA = 0, biB = 0;
    for (int k = 0; k < KDIM; k++) {
        u64 da0 = 0ull, da1 = 0ull, db0 = 0ull, db1 = 0ull;  // {0,0} packed
        const ulonglong2* row = smq + k * 16;
        #pragma unroll
        for (int i = 0; i < 16; i++) {
            ulonglong2 q = row[i];
            fma2(da0, xa[2 * i],     q.x);
            fma2(da1, xa[2 * i + 1], q.y);
            fma2(db0, xb[2 * i],     q.x);
            fma2(db1, xb[2 * i + 1], q.y);
        }
        float a0, a1, a2, a3, c0, c1, c2, c3;
        unpack2(da0, a0, a1); unpack2(da1, a2, a3);
        unpack2(db0, c0, c1); unpack2(db1, c2, c3);
        float dA = (a0 + a1) + (a2 + a3);
        float dB = (c0 + c1) + (c2 + c3);
        if (dA > bestA) { bestA = dA; biA = k; }
        if (dB > bestB) { bestB = dB; biB = k; }
    }

    float* dstA = g_sum + biA * HDIM;
    #pragma unroll
    for (int i = 0; i < 16; i++) {
        float f0, f1, f2, f3;
        unpack2(xa[2 * i], f0, f1); unpack2(xa[2 * i + 1], f2, f3);
        asm volatile("red.global.add.v4.f32 [%0], {%1,%2,%3,%4};"
                     :: "l"(dstA + 4 * i), "f"(f0), "f"(f1), "f"(f2), "f"(f3) : "memory");
    }
    atomicAdd(g_cnt + biA, 1.0f);

    float* dstB = g_sum + biB * HDIM;
    #pragma unroll
    for (int i = 0; i < 16; i++) {
        float f0, f1, f2, f3;
        unpack2(xb[2 * i], f0, f1); unpack2(xb[2 * i + 1], f2, f3);
        asm volatile("red.global.add.v4.f32 [%0], {%1,%2,%3,%4};"
                     :: "l"(dstB + 4 * i), "f"(f0), "f"(f1), "f"(f2), "f"(f3) : "memory");
    }
    atomicAdd(g_cnt + biB, 1.0f);
}

// ---------------------------------------------------------------------------
// update: m = m*RATE + (sum/(cnt+eps))*(1-RATE); refresh mn, nrm; zero sums.
// ---------------------------------------------------------------------------
__global__ void update_kernel() {
    int warp = threadIdx.x >> 5, lane = threadIdx.x & 31;
    int k = blockIdx.x * 8 + warp;
    if (k >= KDIM) return;
    const float IR = 1.0f - RATE_F;
    float sc = IR / (g_cnt[k] + EPS_F);
    float m0 = g_m[k * HDIM + lane]      * RATE_F + g_sum[k * HDIM + lane]      * sc;
    float m1 = g_m[k * HDIM + 32 + lane] * RATE_F + g_sum[k * HDIM + 32 + lane] * sc;
    g_m[k * HDIM + lane]      = m0;
    g_m[k * HDIM + 32 + lane] = m1;
    float ssq = m0 * m0 + m1 * m1;
    #pragma unroll
    for (int o = 16; o; o >>= 1) ssq += __shfl_xor_sync(0xFFFFFFFFu, ssq, o);
    float nrm = sqrtf(ssq);
    float inv = 1.0f / fmaxf(nrm, 1e-12f);
    g_mn[k * HDIM + lane]      = m0 * inv;
    g_mn[k * HDIM + 32 + lane] = m1 * inv;
    g_sum[k * HDIM + lane]      = 0.0f;
    g_sum[k * HDIM + 32 + lane] = 0.0f;
    if (lane == 0) { g_cnt[k] = 0.0f; g_nrm[k] = nrm; }
}

// ---------------------------------------------------------------------------
// out: single pass (score in [-1,1] => exp safe without max-shift).
// m_k reconstructed as mn_k * nrm_k so one mn row load serves dot AND acc.
// dyn smem = 64 KB mn + 1 KB nrm. grid = NPTS/256 x 256.
// ---------------------------------------------------------------------------
__global__ void __launch_bounds__(256, 1) out_kernel(const float* __restrict__ x,
                                                     float* __restrict__ out) {
    extern __shared__ ulonglong2 smem_raw[];
    ulonglong2* smq = smem_raw;                                  // mn: 4096 x 16B
    float* snrm = (float*)(smem_raw + KDIM * HDIM / 4);          // nrm: 256 floats
    const ulonglong2* gm = (const ulonglong2*)g_mn;
    #pragma unroll 4
    for (int i = threadIdx.x; i < KDIM * HDIM / 4; i += 256) smq[i] = gm[i];
    if (threadIdx.x < KDIM) snrm[threadIdx.x] = g_nrm[threadIdx.x];
    __syncthreads();

    int p  = blockIdx.x * 256 + threadIdx.x;
    int b  = p >> 16;
    const float* xb = x + (size_t)b * HDIM * HW + (p & (HW - 1));

    u64 xr[HDIM / 2];
    float s0 = 0.f, s1 = 0.f;
    #pragma unroll
    for (int i = 0; i < HDIM / 2; i++) {
        float f0 = xb[(size_t)(2 * i) * HW];
        float f1 = xb[(size_t)(2 * i + 1) * HW];
        xr[i] = pack2(f0, f1);
        s0 = fmaf(f0, f0, s0);
        s1 = fmaf(f1, f1, s1);
    }
    float invn = 1.0f / fmaxf(sqrtf(s0 + s1), 1e-12f);

    u64 acc[HDIM / 2];
    #pragma unroll
    for (int i = 0; i < HDIM / 2; i++) acc[i] = 0ull;
    float den = 0.0f;

    for (int k = 0; k < KDIM; k++) {
        u64 v[HDIM / 2];
        const ulonglong2* row = smq + k * 16;
        #pragma unroll
        for (int i = 0; i < 16; i++) { ulonglong2 q = row[i]; v[2 * i] = q.x; v[2 * i + 1] = q.y; }

        u64 d0 = 0ull, d1 = 0ull;
        #pragma unroll
        for (int i = 0; i < 16; i++) {
            fma2(d0, xr[2 * i],     v[2 * i]);
            fma2(d1, xr[2 * i + 1], v[2 * i + 1]);
        }
        float e0, e1, e2, e3;
        unpack2(d0, e0, e1); unpack2(d1, e2, e3);
        float d = (e0 + e1) + (e2 + e3);
        float e = __expf(d * invn);
        den += e;
        u64 w2 = pack2(e * snrm[k], e * snrm[k]);
        #pragma unroll
        for (int i = 0; i < HDIM / 2; i++) fma2(acc[i], w2, v[i]);
    }

    float iden = 1.0f / den;
    float* ob = out + (size_t)b * HDIM * HW + (p & (HW - 1));
    #pragma unroll
    for (int i = 0; i < HDIM / 2; i++) {
        float f0, f1;
        unpack2(acc[i], f0, f1);
        ob[(size_t)(2 * i) * HW]     = f0 * iden;
        ob[(size_t)(2 * i + 1) * HW] = f1 * iden;
    }
}

// ---------------------------------------------------------------------------
extern "C" void kernel_launch(void* const* d_in, const int* in_sizes, int n_in,
                              void* d_out, int out_size) {
    const float* x;
    const float* units;
    if (in_sizes[0] >= in_sizes[1]) { x = (const float*)d_in[0]; units = (const float*)d_in[1]; }
    else                            { x = (const float*)d_in[1]; units = (const float*)d_in[0]; }
    float* out = (float*)d_out;

    const int mn_bytes  = KDIM * HDIM * (int)sizeof(float);          // 64 KB
    const int out_bytes = mn_bytes + KDIM * (int)sizeof(float);     // 65 KB
    cudaFuncSetAttribute(assign_kernel, cudaFuncAttributeMaxDynamicSharedMemorySize, mn_bytes);
    cudaFuncSetAttribute(out_kernel,    cudaFuncAttributeMaxDynamicSharedMemorySize, out_bytes);

    prep_kernel<<<32, 256>>>(units);
    for (int it = 0; it < 3; it++) {
        assign_kernel<<<NPTS / 512, 256, mn_bytes>>>(x);
        update_kernel<<<32, 256>>>();
    }
    out_kernel<<<NPTS / 256, 256, out_bytes>>>(x, out);
}